// round 6
// baseline (speedup 1.0000x reference)
#include <cuda_runtime.h>
#include <cuda_bf16.h>

// Shapes (fixed): pos (256,100) f32, neg (256,4096,100) f32, lan (256,100) f32.
// out = mean((pos-lan)^2) + mean(relu(0.1 - mean_d((pos-neg)^2)))

#define B_DIM   256
#define C_DIM   4096
#define D_DIM   100
#define MARGIN  0.1f
#define INV_D   (1.0f / 100.0f)
#define INV_BC  (1.0f / (256.0f * 4096.0f))
#define INV_BD  (1.0f / (256.0f * 100.0f))

// Persistent balanced grid: one wave on 152 SMs x 8 CTAs.
#define NUM_CTAS   1216
#define WARPS_TOT  (NUM_CTAS * 8)                 // 9728
#define NGROUP     ((B_DIM * C_DIM) / 4)          // 262144 groups of 4 rows
#define NSLOT      32

// Device-global scratch (no allocations). Slots 128B apart. Last block resets
// everything each call -> identical state on every graph replay.
__device__ float    g_acc[NSLOT * 32];
__device__ unsigned g_count;

__device__ __forceinline__ float row_partial(float4 p, float4 n) {
    float dx = p.x - n.x, dy = p.y - n.y;
    float dz = p.z - n.z, dw = p.w - n.w;
    return dx * dx + dy * dy + dz * dz + dw * dw;
}

// ---------------------------------------------------------------------------
// Persistent fused kernel. Each warp owns a contiguous range of 4-row groups
// (exact integer split -> imbalance granularity = 1 group). Rows in a range
// are contiguous in memory, so each warp streams one ~43KB linear region.
// ---------------------------------------------------------------------------
__global__ void __launch_bounds__(256, 8)
k_fused(const float* __restrict__ pos,
        const float* __restrict__ neg,
        const float* __restrict__ lan,
        float* __restrict__ out) {
    const int lane  = threadIdx.x & 31;
    const int warp  = threadIdx.x >> 5;
    const bool act  = (lane < 25);        // 25 float4 = 100 floats per row
    const bool hi16 = (lane & 16) != 0;
    const bool hi8  = (lane & 8) != 0;

    // Exact balanced range of groups for this warp.
    const unsigned wid = blockIdx.x * 8u + warp;
    const unsigned g0 = (unsigned)(((unsigned long long)wid     * NGROUP) / WARPS_TOT);
    const unsigned g1 = (unsigned)(((unsigned long long)(wid+1) * NGROUP) / WARPS_TOT);

    float4 p = make_float4(0.f, 0.f, 0.f, 0.f);
    int cur_b = -1;

    float acc2 = 0.f;
    for (unsigned g = g0; g < g1; ++g) {
        const int b  = (int)(g >> 10);           // 1024 groups per b
        const int c0 = (int)(g & 1023u) * 4;

        if (b != cur_b) {                        // <=1 crossing per warp
            if (act) p = *reinterpret_cast<const float4*>(pos + b * D_DIM + lane * 4);
            cur_b = b;
        }

        const float* rb = neg + ((size_t)b * C_DIM + (size_t)c0) * D_DIM + lane * 4;

        float4 n0, n1, n2, n3;
        if (act) {
            n0 = __ldcs(reinterpret_cast<const float4*>(rb + 0 * D_DIM));
            n1 = __ldcs(reinterpret_cast<const float4*>(rb + 1 * D_DIM));
            n2 = __ldcs(reinterpret_cast<const float4*>(rb + 2 * D_DIM));
            n3 = __ldcs(reinterpret_cast<const float4*>(rb + 3 * D_DIM));
        }

        float pa = 0.f, pb = 0.f, pc = 0.f, pd = 0.f;
        if (act) {
            pa = row_partial(p, n0);
            pb = row_partial(p, n1);
            pc = row_partial(p, n2);
            pd = row_partial(p, n3);
        }

        // Combined butterfly: 9 shfls reduce all 4 rows.
        float ua = __shfl_xor_sync(0xffffffffu, pa, 16);
        float ub = __shfl_xor_sync(0xffffffffu, pb, 16);
        float uc = __shfl_xor_sync(0xffffffffu, pc, 16);
        float ud = __shfl_xor_sync(0xffffffffu, pd, 16);
        float e = hi16 ? (pb + ub) : (pa + ua);   // 0-15: a, 16-31: b
        float f = hi16 ? (pd + ud) : (pc + uc);   // 0-15: c, 16-31: d

        float ue = __shfl_xor_sync(0xffffffffu, e, 8);
        float uf = __shfl_xor_sync(0xffffffffu, f, 8);
        float h = hi8 ? (f + uf) : (e + ue);      // 0-7:a, 8-15:c, 16-23:b, 24-31:d

        h += __shfl_xor_sync(0xffffffffu, h, 4);
        h += __shfl_xor_sync(0xffffffffu, h, 2);
        h += __shfl_xor_sync(0xffffffffu, h, 1);

        if ((lane & 7) == 0)                      // lanes 0,8,16,24 hold row sums
            acc2 += fmaxf(0.f, fmaf(h, -INV_D, MARGIN));
    }

    // ---- loss1: blocks 0..255 each handle one b (100 elements) -------------
    float l1 = 0.f;
    if (blockIdx.x < B_DIM && threadIdx.x < D_DIM) {
        int i = blockIdx.x * D_DIM + threadIdx.x;
        float d = pos[i] - lan[i];
        l1 = d * d;
    }

    // ---- warp reduce then block reduce --------------------------------------
    float v = acc2 * INV_BC + l1 * INV_BD;        // LAMDA = 1
    #pragma unroll
    for (int o = 16; o > 0; o >>= 1)
        v += __shfl_xor_sync(0xffffffffu, v, o);

    __shared__ float sred[8];
    if (lane == 0) sred[warp] = v;
    __syncthreads();

    if (threadIdx.x == 0) {
        float t = 0.f;
        #pragma unroll
        for (int w = 0; w < 8; ++w) t += sred[w];
        atomicAdd(&g_acc[(blockIdx.x & (NSLOT - 1)) * 32], t);
        __threadfence();
        unsigned done = atomicAdd(&g_count, 1u);
        if (done == NUM_CTAS - 1) {
            float total = 0.f;
            #pragma unroll
            for (int s = 0; s < NSLOT; ++s) {
                total += atomicAdd(&g_acc[s * 32], 0.0f);  // atomic read
                g_acc[s * 32] = 0.f;                        // reset for replay
            }
            out[0] = total;
            g_count = 0u;
        }
    }
}

extern "C" void kernel_launch(void* const* d_in, const int* in_sizes, int n_in,
                              void* d_out, int out_size) {
    const float* feat_pos = (const float*)d_in[0];
    const float* feat_neg = (const float*)d_in[1];
    const float* feat_lan = (const float*)d_in[2];
    float* out = (float*)d_out;

    k_fused<<<NUM_CTAS, 256>>>(feat_pos, feat_neg, feat_lan, out);
}

// round 7
// speedup vs baseline: 1.0475x; 1.0475x over previous
#include <cuda_runtime.h>
#include <cuda_bf16.h>

// Shapes (fixed): pos (256,100) f32, neg (256,4096,100) f32, lan (256,100) f32.
// out = mean((pos-lan)^2) + mean(relu(0.1 - mean_d((pos-neg)^2)))

#define B_DIM   256
#define C_DIM   4096
#define D_DIM   100
#define MARGIN  0.1f
#define INV_D   (1.0f / 100.0f)
#define INV_BC  (1.0f / (256.0f * 4096.0f))
#define INV_BD  (1.0f / (256.0f * 100.0f))
#define GRID_X  (B_DIM * 16)   // 4096 blocks
#define NSLOT   32

// Device-global scratch (no allocations). Slots 128B apart (own L2 lines).
// Last block resets everything each call -> identical state every replay.
__device__ float    g_acc[NSLOT * 32];
__device__ unsigned g_count;

__device__ __forceinline__ float row_partial(float4 p, float4 n) {
    float dx = p.x - n.x, dy = p.y - n.y;
    float dz = p.z - n.z, dw = p.w - n.w;
    return dx * dx + dy * dy + dz * dz + dw * dw;
}

// ---------------------------------------------------------------------------
// Fused kernel. grid = 4096 (16 chunks of 256 c-rows per b), block = 256.
// WARP-INTERLEAVED group order: at iteration t, warp w handles group t*8+w,
// so the block's 8 warps load 32 CONSECUTIVE rows (one sliding 12.8KB window)
// simultaneously -> maximal DRAM row-buffer locality + same-cycle sector
// sharing at row boundaries. Rows reduced 4-at-a-time (9 shfls / 4 rows).
// ---------------------------------------------------------------------------
__global__ void __launch_bounds__(256)
k_fused(const float* __restrict__ pos,
        const float* __restrict__ neg,
        const float* __restrict__ lan,
        float* __restrict__ out) {
    const int lane  = threadIdx.x & 31;
    const int warp  = threadIdx.x >> 5;
    const int b     = blockIdx.x >> 4;    // / 16
    const int chunk = blockIdx.x & 15;    // % 16
    const bool act  = (lane < 25);        // 25 float4 = 100 floats per row
    const bool hi16 = (lane & 16) != 0;
    const bool hi8  = (lane & 8) != 0;

    float4 p = make_float4(0.f, 0.f, 0.f, 0.f);
    if (act) p = *reinterpret_cast<const float4*>(pos + b * D_DIM + lane * 4);

    // Block-contiguous base; warp w starts at group w, strides by 8 groups.
    const float* base = neg + ((size_t)b * C_DIM + (size_t)chunk * 256) * D_DIM
                        + (size_t)warp * 4 * D_DIM + lane * 4;

    float acc2 = 0.f;
    #pragma unroll 2
    for (int it = 0; it < 8; ++it) {
        // iteration stride: 8 warps * 4 rows * D = 3200 floats
        const float* rb = base + (size_t)it * (8 * 4 * D_DIM);

        float4 n0, n1, n2, n3;
        if (act) {
            n0 = __ldcs(reinterpret_cast<const float4*>(rb + 0 * D_DIM));
            n1 = __ldcs(reinterpret_cast<const float4*>(rb + 1 * D_DIM));
            n2 = __ldcs(reinterpret_cast<const float4*>(rb + 2 * D_DIM));
            n3 = __ldcs(reinterpret_cast<const float4*>(rb + 3 * D_DIM));
        }

        float pa = 0.f, pb = 0.f, pc = 0.f, pd = 0.f;
        if (act) {
            pa = row_partial(p, n0);
            pb = row_partial(p, n1);
            pc = row_partial(p, n2);
            pd = row_partial(p, n3);
        }

        // Combined butterfly: 9 shfls reduce all 4 rows.
        float ua = __shfl_xor_sync(0xffffffffu, pa, 16);
        float ub = __shfl_xor_sync(0xffffffffu, pb, 16);
        float uc = __shfl_xor_sync(0xffffffffu, pc, 16);
        float ud = __shfl_xor_sync(0xffffffffu, pd, 16);
        float e = hi16 ? (pb + ub) : (pa + ua);   // 0-15: a, 16-31: b
        float f = hi16 ? (pd + ud) : (pc + uc);   // 0-15: c, 16-31: d

        float ue = __shfl_xor_sync(0xffffffffu, e, 8);
        float uf = __shfl_xor_sync(0xffffffffu, f, 8);
        float g = hi8 ? (f + uf) : (e + ue);      // 0-7:a, 8-15:c, 16-23:b, 24-31:d

        g += __shfl_xor_sync(0xffffffffu, g, 4);
        g += __shfl_xor_sync(0xffffffffu, g, 2);
        g += __shfl_xor_sync(0xffffffffu, g, 1);

        if ((lane & 7) == 0)                      // lanes 0,8,16,24 hold row sums
            acc2 += fmaxf(0.f, fmaf(g, -INV_D, MARGIN));
    }

    // ---- loss1: chunk-0 blocks handle their b's 100 elements ---------------
    float l1 = 0.f;
    if (chunk == 0 && threadIdx.x < D_DIM) {
        float d = pos[b * D_DIM + threadIdx.x] - lan[b * D_DIM + threadIdx.x];
        l1 = d * d;
    }

    // ---- warp reduce then block reduce --------------------------------------
    float v = acc2 * INV_BC + l1 * INV_BD;        // LAMDA = 1
    #pragma unroll
    for (int o = 16; o > 0; o >>= 1)
        v += __shfl_xor_sync(0xffffffffu, v, o);

    __shared__ float sred[8];
    if (lane == 0) sred[warp] = v;
    __syncthreads();

    if (threadIdx.x == 0) {
        float t = 0.f;
        #pragma unroll
        for (int w = 0; w < 8; ++w) t += sred[w];
        atomicAdd(&g_acc[(blockIdx.x & (NSLOT - 1)) * 32], t);
        __threadfence();
        unsigned done = atomicAdd(&g_count, 1u);
        if (done == GRID_X - 1) {
            float total = 0.f;
            #pragma unroll
            for (int s = 0; s < NSLOT; ++s) {
                total += atomicAdd(&g_acc[s * 32], 0.0f);  // atomic read
                g_acc[s * 32] = 0.f;                        // reset for replay
            }
            out[0] = total;
            g_count = 0u;
        }
    }
}

extern "C" void kernel_launch(void* const* d_in, const int* in_sizes, int n_in,
                              void* d_out, int out_size) {
    const float* feat_pos = (const float*)d_in[0];
    const float* feat_neg = (const float*)d_in[1];
    const float* feat_lan = (const float*)d_in[2];
    float* out = (float*)d_out;

    k_fused<<<GRID_X, 256>>>(feat_pos, feat_neg, feat_lan, out);
}